// round 6
// baseline (speedup 1.0000x reference)
#include <cuda_runtime.h>
#include <cuda_fp16.h>
#include <cstdint>

#define N_NODES 100000
#define N_EDGES 1600000
#define NFEAT   128
#define NHID    64
#define NCLASS  16
#define NT_SCAN 1024
#define CHUNK   98          // 1024 * 98 = 100352 >= N_NODES

// Scratch (device globals — no allocation allowed in kernel_launch)
__device__ __half g_h1h[N_NODES * NHID];    // X @ W1 (fp16, gathered)
__device__ __half g_h2h[N_NODES * NCLASS];  // layer-2 features (fp16, gathered)
__device__ int    g_hist[N_NODES];          // in-degree histogram (graph 1)
__device__ int    g_off[N_NODES];           // CSR bin start
__device__ int    g_cur[N_NODES];           // permute cursor (== bin end after permute)
__device__ uint2  g_sorted[N_EDGES];        // {src, weight} sorted by dst

// ---------------- f32x2 packed helpers (SASS FFMA2 — only via PTX) ----------
__device__ __forceinline__ void fma2(unsigned long long& d,
                                     unsigned long long a,
                                     unsigned long long b) {
    asm("fma.rn.f32x2 %0, %1, %2, %3;" : "=l"(d) : "l"(a), "l"(b), "l"(d));
}
__device__ __forceinline__ unsigned long long add2(unsigned long long a,
                                                   unsigned long long b) {
    unsigned long long r;
    asm("add.rn.f32x2 %0, %1, %2;" : "=l"(r) : "l"(a), "l"(b));
    return r;
}
__device__ __forceinline__ unsigned long long pack2(float a) {
    unsigned long long r;
    asm("mov.b64 %0, {%1, %1};" : "=l"(r) : "f"(a));
    return r;
}
__device__ __forceinline__ unsigned long long packf2(float2 f) {
    unsigned long long r;
    asm("mov.b64 %0, {%1, %2};" : "=l"(r) : "f"(f.x), "f"(f.y));
    return r;
}
__device__ __forceinline__ float2 unpack2(unsigned long long p) {
    float2 f;
    asm("mov.b64 {%0, %1}, %2;" : "=f"(f.x), "=f"(f.y) : "l"(p));
    return f;
}
__device__ __forceinline__ uint32_t f2tf32(float f) {
    uint32_t r;
    asm("cvt.rna.tf32.f32 %0, %1;" : "=r"(r) : "f"(f));
    return r;
}

// ---------------------------------------------------------------------------
// Zero d_out (atomically accumulated by scatter2) and the histogram.
// ---------------------------------------------------------------------------
__global__ void zero_kernel(float* __restrict__ out) {
    const int stride = gridDim.x * blockDim.x;
    int i = blockIdx.x * blockDim.x + threadIdx.x;
    const int n2 = N_NODES * NCLASS / 4;
    const float4 z = make_float4(0.f, 0.f, 0.f, 0.f);
    for (int idx = i; idx < n2; idx += stride)
        reinterpret_cast<float4*>(out)[idx] = z;
    for (int idx = i; idx < N_NODES; idx += stride)
        g_hist[idx] = 0;
}

// ---------------------------------------------------------------------------
// GEMM1 (tf32 tensor cores): h1 = X[100000,128] @ W1[128,64], fp16 output.
// ---------------------------------------------------------------------------
__global__ __launch_bounds__(256) void gemm1_kernel(const float* __restrict__ X,
                                                    const float* __restrict__ W) {
    __shared__ float Xs[128][36];
    __shared__ float Ws[32][72];

    const int tid  = threadIdx.x;
    const int lane = tid & 31;
    const int warp = tid >> 5;
    const int m0   = blockIdx.x * 128;
    const int wm   = warp >> 1;
    const int wn   = warp & 1;
    const int gr   = lane >> 2;
    const int tg   = lane & 3;

    float acc[2][4][4];
#pragma unroll
    for (int mi = 0; mi < 2; mi++)
#pragma unroll
        for (int ni = 0; ni < 4; ni++)
#pragma unroll
            for (int r = 0; r < 4; r++) acc[mi][ni][r] = 0.f;

    for (int kc = 0; kc < NFEAT; kc += 32) {
        __syncthreads();
#pragma unroll
        for (int t = 0; t < 4; t++) {
            int f4  = tid + t * 256;
            int row = f4 >> 3;
            int c4  = (f4 & 7) * 4;
            int gm  = m0 + row;
            float4 v = make_float4(0.f, 0.f, 0.f, 0.f);
            if (gm < N_NODES)
                v = *reinterpret_cast<const float4*>(&X[gm * NFEAT + kc + c4]);
            Xs[row][c4 + 0] = __uint_as_float(f2tf32(v.x));
            Xs[row][c4 + 1] = __uint_as_float(f2tf32(v.y));
            Xs[row][c4 + 2] = __uint_as_float(f2tf32(v.z));
            Xs[row][c4 + 3] = __uint_as_float(f2tf32(v.w));
        }
#pragma unroll
        for (int t = 0; t < 2; t++) {
            int f4  = tid + t * 256;
            int row = f4 >> 4;
            int c4  = (f4 & 15) * 4;
            float4 v = *reinterpret_cast<const float4*>(&W[(kc + row) * NHID + c4]);
            Ws[row][c4 + 0] = __uint_as_float(f2tf32(v.x));
            Ws[row][c4 + 1] = __uint_as_float(f2tf32(v.y));
            Ws[row][c4 + 2] = __uint_as_float(f2tf32(v.z));
            Ws[row][c4 + 3] = __uint_as_float(f2tf32(v.w));
        }
        __syncthreads();

#pragma unroll
        for (int ks = 0; ks < 32; ks += 8) {
            uint32_t a[2][4];
#pragma unroll
            for (int mi = 0; mi < 2; mi++) {
                int base = wm * 32 + mi * 16;
                a[mi][0] = __float_as_uint(Xs[base + gr][ks + tg]);
                a[mi][1] = __float_as_uint(Xs[base + gr + 8][ks + tg]);
                a[mi][2] = __float_as_uint(Xs[base + gr][ks + tg + 4]);
                a[mi][3] = __float_as_uint(Xs[base + gr + 8][ks + tg + 4]);
            }
#pragma unroll
            for (int ni = 0; ni < 4; ni++) {
                int cb = wn * 32 + ni * 8;
                uint32_t b0 = __float_as_uint(Ws[ks + tg][cb + gr]);
                uint32_t b1 = __float_as_uint(Ws[ks + tg + 4][cb + gr]);
#pragma unroll
                for (int mi = 0; mi < 2; mi++) {
                    asm volatile(
                        "mma.sync.aligned.m16n8k8.row.col.f32.tf32.tf32.f32 "
                        "{%0,%1,%2,%3}, {%4,%5,%6,%7}, {%8,%9}, {%0,%1,%2,%3};"
                        : "+f"(acc[mi][ni][0]), "+f"(acc[mi][ni][1]),
                          "+f"(acc[mi][ni][2]), "+f"(acc[mi][ni][3])
                        : "r"(a[mi][0]), "r"(a[mi][1]), "r"(a[mi][2]), "r"(a[mi][3]),
                          "r"(b0), "r"(b1));
                }
            }
        }
    }

#pragma unroll
    for (int mi = 0; mi < 2; mi++) {
#pragma unroll
        for (int ni = 0; ni < 4; ni++) {
            int row = m0 + wm * 32 + mi * 16 + gr;
            int col = wn * 32 + ni * 8 + tg * 2;
            if (row < N_NODES)
                *reinterpret_cast<__half2*>(&g_h1h[row * NHID + col]) =
                    __floats2half2_rn(acc[mi][ni][0], acc[mi][ni][1]);
            if (row + 8 < N_NODES)
                *reinterpret_cast<__half2*>(&g_h1h[(row + 8) * NHID + col]) =
                    __floats2half2_rn(acc[mi][ni][2], acc[mi][ni][3]);
        }
    }
}

// ---------------------------------------------------------------------------
// hist: in-degree of graph 1.
// ---------------------------------------------------------------------------
__global__ __launch_bounds__(256) void hist_kernel(const int* __restrict__ ei) {
    int e = blockIdx.x * blockDim.x + threadIdx.x;
    if (e < N_EDGES) atomicAdd(&g_hist[ei[N_EDGES + e]], 1);
}

// ---------------------------------------------------------------------------
// build_offsets: single block, 1024 threads. Chunk sums -> smem scan ->
// per-chunk walk writing exclusive offsets + cursor copy.
// ---------------------------------------------------------------------------
__global__ __launch_bounds__(NT_SCAN) void build_offsets_kernel() {
    __shared__ int ts[NT_SCAN];
    const int t  = threadIdx.x;
    const int lo = t * CHUNK;
    const int hi = min(lo + CHUNK, N_NODES);

    int s = 0;
    for (int i = lo; i < hi; i++) s += g_hist[i];
    ts[t] = s;
    __syncthreads();
    // inclusive Hillis-Steele scan
    for (int off = 1; off < NT_SCAN; off <<= 1) {
        int v = (t >= off) ? ts[t - off] : 0;
        __syncthreads();
        ts[t] += v;
        __syncthreads();
    }
    int base = ts[t] - s;   // exclusive
    for (int i = lo; i < hi; i++) {
        g_off[i] = base;
        g_cur[i] = base;
        base += g_hist[i];
    }
}

// ---------------------------------------------------------------------------
// permute: bucket edges by dst. g_cur[d] ends at bin end.
// ---------------------------------------------------------------------------
__global__ __launch_bounds__(256) void permute_kernel(const int* __restrict__ ei,
                                                      const float* __restrict__ ew) {
    int e = blockIdx.x * blockDim.x + threadIdx.x;
    if (e >= N_EDGES) return;
    int s = ei[e];
    int d = ei[N_EDGES + e];
    float w = ew[e];
    int pos = atomicAdd(&g_cur[d], 1);
    g_sorted[pos] = make_uint2((unsigned)s, __float_as_uint(w));
}

// ---------------------------------------------------------------------------
// Fused aggregate1 + ReLU + GEMM2: 8 threads per node.
// Each group walks its dst-bin, accumulating 64 fp32 hid values in registers
// (thread j owns hid [j*8, j*8+8)); then computes the 16 W2 outputs via
// FFMA2 partials + 3-round shfl reduce; writes h2 fp16. Zero atomics.
// ---------------------------------------------------------------------------
__global__ __launch_bounds__(256) void agg_gemm2_kernel(const float* __restrict__ W2) {
    __shared__ float Ws[NHID * NCLASS];  // [64][16] row-major
    const int tid = threadIdx.x;
    reinterpret_cast<float4*>(Ws)[tid] = reinterpret_cast<const float4*>(W2)[tid];
    __syncthreads();

    const int gid  = blockIdx.x * 256 + tid;
    const int node = gid >> 3;
    const int j    = gid & 7;            // owns hid cols [j*8, j*8+8)
    if (node >= N_NODES) return;

    const int beg = g_off[node];
    const int end = g_cur[node];

    unsigned long long acc[4] = {};      // 8 fp32 hid values as 4 f32x2

    for (int e = beg; e < end; e++) {
        uint2 sw = g_sorted[e];          // same addr across the 8 lanes -> 1 req
        float w  = __uint_as_float(sw.y);
        unsigned long long wp = pack2(w);
        uint4 raw = *reinterpret_cast<const uint4*>(&g_h1h[sw.x * NHID + j * 8]);
        fma2(acc[0], packf2(__half22float2(*reinterpret_cast<__half2*>(&raw.x))), wp);
        fma2(acc[1], packf2(__half22float2(*reinterpret_cast<__half2*>(&raw.y))), wp);
        fma2(acc[2], packf2(__half22float2(*reinterpret_cast<__half2*>(&raw.z))), wp);
        fma2(acc[3], packf2(__half22float2(*reinterpret_cast<__half2*>(&raw.w))), wp);
    }

    // ReLU + W2 partials: thread j covers k = j*8 .. j*8+7
    float a[8];
#pragma unroll
    for (int p = 0; p < 4; p++) {
        float2 f = unpack2(acc[p]);
        a[2 * p]     = fmaxf(f.x, 0.f);
        a[2 * p + 1] = fmaxf(f.y, 0.f);
    }

    unsigned long long oacc[8] = {};     // 16 outputs as 8 f32x2
#pragma unroll
    for (int k = 0; k < 8; k++) {
        unsigned long long ap = pack2(a[k]);
        const ulonglong2* wr = reinterpret_cast<const ulonglong2*>(
            &Ws[(j * 8 + k) * NCLASS]);
        ulonglong2 w01 = wr[0];
        ulonglong2 w23 = wr[1];
        ulonglong2 w45 = wr[2];
        ulonglong2 w67 = wr[3];
        fma2(oacc[0], ap, w01.x); fma2(oacc[1], ap, w01.y);
        fma2(oacc[2], ap, w23.x); fma2(oacc[3], ap, w23.y);
        fma2(oacc[4], ap, w45.x); fma2(oacc[5], ap, w45.y);
        fma2(oacc[6], ap, w67.x); fma2(oacc[7], ap, w67.y);
    }

    // reduce the 8 split-K partials within the 8-lane group
#pragma unroll
    for (int m = 1; m < 8; m <<= 1)
#pragma unroll
        for (int p = 0; p < 8; p++)
            oacc[p] = add2(oacc[p], __shfl_xor_sync(0xffffffffu, oacc[p], m));

    // lane j writes output cols [2j, 2j+2)
    float2 t2 = unpack2(oacc[j]);
    *reinterpret_cast<__half2*>(&g_h2h[node * NCLASS + 2 * j]) =
        __floats2half2_rn(t2.x, t2.y);
}

// ---------------------------------------------------------------------------
// scatter2: out[dst] += w * h2[src].  4 threads/edge, fp16 gather -> fp32 red.
// ---------------------------------------------------------------------------
__global__ __launch_bounds__(256) void scatter2_kernel(const int* __restrict__ ei,
                                                       const float* __restrict__ ew,
                                                       float* __restrict__ out) {
    int gid = blockIdx.x * blockDim.x + threadIdx.x;
    int e = gid >> 2;
    int c = gid & 3;
    if (e >= N_EDGES) return;
    int s = ei[e];
    int d = ei[N_EDGES + e];
    float w = ew[e];
    uint2 raw = *reinterpret_cast<const uint2*>(&g_h2h[s * NCLASS + c * 4]);
    float2 f0 = __half22float2(*reinterpret_cast<__half2*>(&raw.x));
    float2 f1 = __half22float2(*reinterpret_cast<__half2*>(&raw.y));
    float* dst = &out[d * NCLASS + c * 4];
    asm volatile("red.global.add.v4.f32 [%0], {%1, %2, %3, %4};"
                 :: "l"(dst), "f"(f0.x * w), "f"(f0.y * w), "f"(f1.x * w), "f"(f1.y * w)
                 : "memory");
}

// ---------------------------------------------------------------------------
extern "C" void kernel_launch(void* const* d_in, const int* in_sizes, int n_in,
                              void* d_out, int out_size) {
    const float* x   = (const float*)d_in[0];
    const int*   ei1 = (const int*)  d_in[1];
    const int*   ei2 = (const int*)  d_in[2];
    const float* ew1 = (const float*)d_in[3];
    const float* ew2 = (const float*)d_in[4];
    const float* W1  = (const float*)d_in[5];
    const float* W2  = (const float*)d_in[6];
    float* out = (float*)d_out;

    zero_kernel<<<1024, 256>>>(out);
    gemm1_kernel<<<(N_NODES + 127) / 128, 256>>>(x, W1);
    hist_kernel<<<(N_EDGES + 255) / 256, 256>>>(ei1);
    build_offsets_kernel<<<1, NT_SCAN>>>();
    permute_kernel<<<(N_EDGES + 255) / 256, 256>>>(ei1, ew1);
    agg_gemm2_kernel<<<(N_NODES * 8 + 255) / 256, 256>>>(W2);
    scatter2_kernel<<<(N_EDGES * 4 + 255) / 256, 256>>>(ei2, ew2, out);
}

// round 7
// speedup vs baseline: 1.0169x; 1.0169x over previous
#include <cuda_runtime.h>
#include <cuda_fp16.h>
#include <cstdint>

#define N_NODES 100000
#define N_EDGES 1600000
#define NFEAT   128
#define NHID    64
#define NCLASS  16
#define NBLK_SC 400          // scan blocks: 400*256 = 102400 >= N_NODES

// Scratch (device globals — no allocation allowed in kernel_launch)
__device__ __half g_h1h[N_NODES * NHID];    // X @ W1 (fp16, gathered)
__device__ __half g_h2h[N_NODES * NCLASS];  // layer-2 features (fp16, gathered)
__device__ int    g_hist[N_NODES];          // in-degree histogram (graph 1)
__device__ int    g_off[N_NODES];           // CSR bin start
__device__ int    g_cur[N_NODES];           // permute cursor (== bin end after permute)
__device__ int    g_bsum[NBLK_SC];          // scan block partials
__device__ int    g_bbase[NBLK_SC];         // scan block exclusive bases
__device__ uint2  g_sorted[N_EDGES];        // {src, weight} sorted by dst

// ---------------- f32x2 packed helpers (SASS FFMA2 — only via PTX) ----------
__device__ __forceinline__ void fma2(unsigned long long& d,
                                     unsigned long long a,
                                     unsigned long long b) {
    asm("fma.rn.f32x2 %0, %1, %2, %3;" : "=l"(d) : "l"(a), "l"(b), "l"(d));
}
__device__ __forceinline__ unsigned long long add2(unsigned long long a,
                                                   unsigned long long b) {
    unsigned long long r;
    asm("add.rn.f32x2 %0, %1, %2;" : "=l"(r) : "l"(a), "l"(b));
    return r;
}
__device__ __forceinline__ unsigned long long pack2(float a) {
    unsigned long long r;
    asm("mov.b64 %0, {%1, %1};" : "=l"(r) : "f"(a));
    return r;
}
__device__ __forceinline__ unsigned long long packf2(float2 f) {
    unsigned long long r;
    asm("mov.b64 %0, {%1, %2};" : "=l"(r) : "f"(f.x), "f"(f.y));
    return r;
}
__device__ __forceinline__ float2 unpack2(unsigned long long p) {
    float2 f;
    asm("mov.b64 {%0, %1}, %2;" : "=f"(f.x), "=f"(f.y) : "l"(p));
    return f;
}
__device__ __forceinline__ uint32_t f2tf32(float f) {
    uint32_t r;
    asm("cvt.rna.tf32.f32 %0, %1;" : "=r"(r) : "f"(f));
    return r;
}

// ---------------------------------------------------------------------------
// Zero d_out (atomically accumulated by scatter2) and the histogram.
// ---------------------------------------------------------------------------
__global__ void zero_kernel(float* __restrict__ out) {
    const int stride = gridDim.x * blockDim.x;
    int i = blockIdx.x * blockDim.x + threadIdx.x;
    const int n2 = N_NODES * NCLASS / 4;
    const float4 z = make_float4(0.f, 0.f, 0.f, 0.f);
    for (int idx = i; idx < n2; idx += stride)
        reinterpret_cast<float4*>(out)[idx] = z;
    for (int idx = i; idx < N_NODES; idx += stride)
        g_hist[idx] = 0;
}

// ---------------------------------------------------------------------------
// GEMM1 (tf32 tensor cores): h1 = X[100000,128] @ W1[128,64], fp16 output.
// ---------------------------------------------------------------------------
__global__ __launch_bounds__(256) void gemm1_kernel(const float* __restrict__ X,
                                                    const float* __restrict__ W) {
    __shared__ float Xs[128][36];
    __shared__ float Ws[32][72];

    const int tid  = threadIdx.x;
    const int lane = tid & 31;
    const int warp = tid >> 5;
    const int m0   = blockIdx.x * 128;
    const int wm   = warp >> 1;
    const int wn   = warp & 1;
    const int gr   = lane >> 2;
    const int tg   = lane & 3;

    float acc[2][4][4];
#pragma unroll
    for (int mi = 0; mi < 2; mi++)
#pragma unroll
        for (int ni = 0; ni < 4; ni++)
#pragma unroll
            for (int r = 0; r < 4; r++) acc[mi][ni][r] = 0.f;

    for (int kc = 0; kc < NFEAT; kc += 32) {
        __syncthreads();
#pragma unroll
        for (int t = 0; t < 4; t++) {
            int f4  = tid + t * 256;
            int row = f4 >> 3;
            int c4  = (f4 & 7) * 4;
            int gm  = m0 + row;
            float4 v = make_float4(0.f, 0.f, 0.f, 0.f);
            if (gm < N_NODES)
                v = *reinterpret_cast<const float4*>(&X[gm * NFEAT + kc + c4]);
            Xs[row][c4 + 0] = __uint_as_float(f2tf32(v.x));
            Xs[row][c4 + 1] = __uint_as_float(f2tf32(v.y));
            Xs[row][c4 + 2] = __uint_as_float(f2tf32(v.z));
            Xs[row][c4 + 3] = __uint_as_float(f2tf32(v.w));
        }
#pragma unroll
        for (int t = 0; t < 2; t++) {
            int f4  = tid + t * 256;
            int row = f4 >> 4;
            int c4  = (f4 & 15) * 4;
            float4 v = *reinterpret_cast<const float4*>(&W[(kc + row) * NHID + c4]);
            Ws[row][c4 + 0] = __uint_as_float(f2tf32(v.x));
            Ws[row][c4 + 1] = __uint_as_float(f2tf32(v.y));
            Ws[row][c4 + 2] = __uint_as_float(f2tf32(v.z));
            Ws[row][c4 + 3] = __uint_as_float(f2tf32(v.w));
        }
        __syncthreads();

#pragma unroll
        for (int ks = 0; ks < 32; ks += 8) {
            uint32_t a[2][4];
#pragma unroll
            for (int mi = 0; mi < 2; mi++) {
                int base = wm * 32 + mi * 16;
                a[mi][0] = __float_as_uint(Xs[base + gr][ks + tg]);
                a[mi][1] = __float_as_uint(Xs[base + gr + 8][ks + tg]);
                a[mi][2] = __float_as_uint(Xs[base + gr][ks + tg + 4]);
                a[mi][3] = __float_as_uint(Xs[base + gr + 8][ks + tg + 4]);
            }
#pragma unroll
            for (int ni = 0; ni < 4; ni++) {
                int cb = wn * 32 + ni * 8;
                uint32_t b0 = __float_as_uint(Ws[ks + tg][cb + gr]);
                uint32_t b1 = __float_as_uint(Ws[ks + tg + 4][cb + gr]);
#pragma unroll
                for (int mi = 0; mi < 2; mi++) {
                    asm volatile(
                        "mma.sync.aligned.m16n8k8.row.col.f32.tf32.tf32.f32 "
                        "{%0,%1,%2,%3}, {%4,%5,%6,%7}, {%8,%9}, {%0,%1,%2,%3};"
                        : "+f"(acc[mi][ni][0]), "+f"(acc[mi][ni][1]),
                          "+f"(acc[mi][ni][2]), "+f"(acc[mi][ni][3])
                        : "r"(a[mi][0]), "r"(a[mi][1]), "r"(a[mi][2]), "r"(a[mi][3]),
                          "r"(b0), "r"(b1));
                }
            }
        }
    }

#pragma unroll
    for (int mi = 0; mi < 2; mi++) {
#pragma unroll
        for (int ni = 0; ni < 4; ni++) {
            int row = m0 + wm * 32 + mi * 16 + gr;
            int col = wn * 32 + ni * 8 + tg * 2;
            if (row < N_NODES)
                *reinterpret_cast<__half2*>(&g_h1h[row * NHID + col]) =
                    __floats2half2_rn(acc[mi][ni][0], acc[mi][ni][1]);
            if (row + 8 < N_NODES)
                *reinterpret_cast<__half2*>(&g_h1h[(row + 8) * NHID + col]) =
                    __floats2half2_rn(acc[mi][ni][2], acc[mi][ni][3]);
        }
    }
}

// ---------------------------------------------------------------------------
// hist: in-degree of graph 1.
// ---------------------------------------------------------------------------
__global__ __launch_bounds__(256) void hist_kernel(const int* __restrict__ ei) {
    int e = blockIdx.x * blockDim.x + threadIdx.x;
    if (e < N_EDGES) atomicAdd(&g_hist[ei[N_EDGES + e]], 1);
}

// ---------------------------------------------------------------------------
// Parallel exclusive scan of g_hist -> g_off/g_cur. Three tiny kernels.
// ---------------------------------------------------------------------------
__global__ __launch_bounds__(256) void scan_partial_kernel() {
    __shared__ int ws[8];
    const int t = threadIdx.x;
    int idx = blockIdx.x * 256 + t;
    int v = (idx < N_NODES) ? g_hist[idx] : 0;
    // warp reduce
    int s = v;
#pragma unroll
    for (int m = 16; m; m >>= 1) s += __shfl_xor_sync(0xffffffffu, s, m);
    if ((t & 31) == 0) ws[t >> 5] = s;
    __syncthreads();
    if (t == 0) {
        int tot = 0;
#pragma unroll
        for (int i = 0; i < 8; i++) tot += ws[i];
        g_bsum[blockIdx.x] = tot;
    }
}

__global__ __launch_bounds__(512) void scan_mid_kernel() {
    __shared__ int ts[512];
    const int t = threadIdx.x;
    int v = (t < NBLK_SC) ? g_bsum[t] : 0;
    ts[t] = v;
    __syncthreads();
    for (int off = 1; off < 512; off <<= 1) {
        int u = (t >= off) ? ts[t - off] : 0;
        __syncthreads();
        ts[t] += u;
        __syncthreads();
    }
    if (t < NBLK_SC) g_bbase[t] = ts[t] - v;   // exclusive
}

__global__ __launch_bounds__(256) void scan_final_kernel() {
    __shared__ int ts[256];
    const int t = threadIdx.x;
    int idx = blockIdx.x * 256 + t;
    int v = (idx < N_NODES) ? g_hist[idx] : 0;
    ts[t] = v;
    __syncthreads();
    for (int off = 1; off < 256; off <<= 1) {
        int u = (t >= off) ? ts[t - off] : 0;
        __syncthreads();
        ts[t] += u;
        __syncthreads();
    }
    if (idx < N_NODES) {
        int o = g_bbase[blockIdx.x] + ts[t] - v;   // exclusive within block + base
        g_off[idx] = o;
        g_cur[idx] = o;
    }
}

// ---------------------------------------------------------------------------
// permute: bucket edges by dst. g_cur[d] ends at bin end.
// ---------------------------------------------------------------------------
__global__ __launch_bounds__(256) void permute_kernel(const int* __restrict__ ei,
                                                      const float* __restrict__ ew) {
    int e = blockIdx.x * blockDim.x + threadIdx.x;
    if (e >= N_EDGES) return;
    int s = ei[e];
    int d = ei[N_EDGES + e];
    float w = ew[e];
    int pos = atomicAdd(&g_cur[d], 1);
    g_sorted[pos] = make_uint2((unsigned)s, __float_as_uint(w));
}

// ---------------------------------------------------------------------------
// Fused aggregate1 + ReLU + GEMM2: ONE WARP per node.
// Per edge: g_sorted[e] broadcast + 32 lanes x 4B = one coalesced 128B row of
// h1 (rows are 128B aligned). Lane owns hid pair [2*lane, 2*lane+1], fp32
// accumulate (f32x2). Bin walk unrolled x2 for MLP. Then ReLU + W2 partials
// and a 5-round butterfly; lanes 0-7 write the 16 fp16 outputs. Zero atomics.
// ---------------------------------------------------------------------------
__global__ __launch_bounds__(256) void agg_gemm2_kernel(const float* __restrict__ W2) {
    __shared__ float Ws[NHID * NCLASS];  // [64][16] row-major
    const int tid = threadIdx.x;
    reinterpret_cast<float4*>(Ws)[tid] = reinterpret_cast<const float4*>(W2)[tid];
    __syncthreads();

    const int lane = tid & 31;
    const int node = blockIdx.x * 8 + (tid >> 5);
    if (node >= N_NODES) return;

    const int beg = g_off[node];
    const int end = g_cur[node];

    unsigned long long acc = 0;          // hid pair [2*lane, 2*lane+1] fp32

    const uint32_t* h1u = reinterpret_cast<const uint32_t*>(g_h1h);
    int e = beg;
    for (; e + 2 <= end; e += 2) {
        uint2 sw0 = g_sorted[e];
        uint2 sw1 = g_sorted[e + 1];
        uint32_t r0 = h1u[sw0.x * 32 + lane];
        uint32_t r1 = h1u[sw1.x * 32 + lane];
        fma2(acc, packf2(__half22float2(*reinterpret_cast<__half2*>(&r0))),
             pack2(__uint_as_float(sw0.y)));
        fma2(acc, packf2(__half22float2(*reinterpret_cast<__half2*>(&r1))),
             pack2(__uint_as_float(sw1.y)));
    }
    if (e < end) {
        uint2 sw0 = g_sorted[e];
        uint32_t r0 = h1u[sw0.x * 32 + lane];
        fma2(acc, packf2(__half22float2(*reinterpret_cast<__half2*>(&r0))),
             pack2(__uint_as_float(sw0.y)));
    }

    // ReLU
    float2 af = unpack2(acc);
    float a0 = fmaxf(af.x, 0.f);
    float a1 = fmaxf(af.y, 0.f);

    // W2 partials: lane covers k = 2*lane, 2*lane+1
    unsigned long long oacc[8];
    {
        unsigned long long p0 = pack2(a0);
        unsigned long long p1 = pack2(a1);
        const ulonglong2* w0 = reinterpret_cast<const ulonglong2*>(&Ws[(2 * lane) * NCLASS]);
        const ulonglong2* w1 = reinterpret_cast<const ulonglong2*>(&Ws[(2 * lane + 1) * NCLASS]);
#pragma unroll
        for (int q = 0; q < 4; q++) {
            ulonglong2 wa = w0[q];
            ulonglong2 wb = w1[q];
            unsigned long long t0 = 0, t1 = 0;
            fma2(t0, p0, wa.x); fma2(t0, p1, wb.x);
            fma2(t1, p0, wa.y); fma2(t1, p1, wb.y);
            oacc[2 * q]     = t0;
            oacc[2 * q + 1] = t1;
        }
    }

    // butterfly reduce across 32 lanes
#pragma unroll
    for (int m = 1; m < 32; m <<= 1)
#pragma unroll
        for (int p = 0; p < 8; p++)
            oacc[p] = add2(oacc[p], __shfl_xor_sync(0xffffffffu, oacc[p], m));

    // lanes 0-7: lane j writes output cols [2j, 2j+2)
    if (lane < 8) {
        float2 t2 = unpack2(oacc[lane]);
        *reinterpret_cast<__half2*>(&g_h2h[node * NCLASS + 2 * lane]) =
            __floats2half2_rn(t2.x, t2.y);
    }
}

// ---------------------------------------------------------------------------
// scatter2: out[dst] += w * h2[src].  4 threads/edge, fp16 gather -> fp32 red.
// ---------------------------------------------------------------------------
__global__ __launch_bounds__(256) void scatter2_kernel(const int* __restrict__ ei,
                                                       const float* __restrict__ ew,
                                                       float* __restrict__ out) {
    int gid = blockIdx.x * blockDim.x + threadIdx.x;
    int e = gid >> 2;
    int c = gid & 3;
    if (e >= N_EDGES) return;
    int s = ei[e];
    int d = ei[N_EDGES + e];
    float w = ew[e];
    uint2 raw = *reinterpret_cast<const uint2*>(&g_h2h[s * NCLASS + c * 4]);
    float2 f0 = __half22float2(*reinterpret_cast<__half2*>(&raw.x));
    float2 f1 = __half22float2(*reinterpret_cast<__half2*>(&raw.y));
    float* dst = &out[d * NCLASS + c * 4];
    asm volatile("red.global.add.v4.f32 [%0], {%1, %2, %3, %4};"
                 :: "l"(dst), "f"(f0.x * w), "f"(f0.y * w), "f"(f1.x * w), "f"(f1.y * w)
                 : "memory");
}

// ---------------------------------------------------------------------------
extern "C" void kernel_launch(void* const* d_in, const int* in_sizes, int n_in,
                              void* d_out, int out_size) {
    const float* x   = (const float*)d_in[0];
    const int*   ei1 = (const int*)  d_in[1];
    const int*   ei2 = (const int*)  d_in[2];
    const float* ew1 = (const float*)d_in[3];
    const float* ew2 = (const float*)d_in[4];
    const float* W1  = (const float*)d_in[5];
    const float* W2  = (const float*)d_in[6];
    float* out = (float*)d_out;

    zero_kernel<<<1024, 256>>>(out);
    gemm1_kernel<<<(N_NODES + 127) / 128, 256>>>(x, W1);
    hist_kernel<<<(N_EDGES + 255) / 256, 256>>>(ei1);
    scan_partial_kernel<<<NBLK_SC, 256>>>();
    scan_mid_kernel<<<1, 512>>>();
    scan_final_kernel<<<NBLK_SC, 256>>>();
    permute_kernel<<<(N_EDGES + 255) / 256, 256>>>(ei1, ew1);
    agg_gemm2_kernel<<<(N_NODES + 7) / 8, 256>>>(W2);
    scatter2_kernel<<<(N_EDGES * 4 + 255) / 256, 256>>>(ei2, ew2, out);
}

// round 8
// speedup vs baseline: 1.8699x; 1.8388x over previous
#include <cuda_runtime.h>
#include <cstdint>

#define N_NODES 100000
#define N_EDGES 1600000
#define NFEAT   128
#define NHID    64
#define NCLASS  16

// Scratch (device globals — no allocation allowed in kernel_launch)
__device__ float g_h1[N_NODES * NHID];     // X @ W1 (fp32)
__device__ float g_agg1[N_NODES * NHID];   // scatter1 accumulator
__device__ float g_h2[N_NODES * NCLASS];   // relu(agg1) @ W2

// ---------------- f32x2 packed helpers (SASS FFMA2 — only via PTX) ----------
__device__ __forceinline__ void fma2(unsigned long long& d,
                                     unsigned long long a,
                                     unsigned long long b) {
    asm("fma.rn.f32x2 %0, %1, %2, %3;" : "=l"(d) : "l"(a), "l"(b), "l"(d));
}
__device__ __forceinline__ unsigned long long pack2(float a) {
    unsigned long long r;
    asm("mov.b64 %0, {%1, %1};" : "=l"(r) : "f"(a));
    return r;
}
__device__ __forceinline__ float2 unpack2(unsigned long long p) {
    float2 f;
    asm("mov.b64 {%0, %1}, %2;" : "=f"(f.x), "=f"(f.y) : "l"(p));
    return f;
}
__device__ __forceinline__ uint32_t f2tf32(float f) {
    uint32_t r;
    asm("cvt.rna.tf32.f32 %0, %1;" : "=r"(r) : "f"(f));
    return r;
}

// ---------------------------------------------------------------------------
// Zero agg1 and d_out (atomically accumulated; must start at 0 every launch).
// ---------------------------------------------------------------------------
__global__ void zero_kernel(float* __restrict__ out) {
    const int stride = gridDim.x * blockDim.x;
    int i = blockIdx.x * blockDim.x + threadIdx.x;
    const float4 z = make_float4(0.f, 0.f, 0.f, 0.f);
    const int n1 = N_NODES * NHID / 4;
    const int n2 = N_NODES * NCLASS / 4;
    for (int idx = i; idx < n1; idx += stride)
        reinterpret_cast<float4*>(g_agg1)[idx] = z;
    for (int idx = i; idx < n2; idx += stride)
        reinterpret_cast<float4*>(out)[idx] = z;
}

// ---------------------------------------------------------------------------
// GEMM1 (tf32 tensor cores): h1 = X[100000,128] @ W1[128,64], fp32 output.
// Block: 256 threads = 8 warps, tile 128(M) x 64(N), K chunks of 32.
// ---------------------------------------------------------------------------
__global__ __launch_bounds__(256) void gemm1_kernel(const float* __restrict__ X,
                                                    const float* __restrict__ W) {
    __shared__ float Xs[128][36];
    __shared__ float Ws[32][72];

    const int tid  = threadIdx.x;
    const int lane = tid & 31;
    const int warp = tid >> 5;
    const int m0   = blockIdx.x * 128;
    const int wm   = warp >> 1;
    const int wn   = warp & 1;
    const int gr   = lane >> 2;
    const int tg   = lane & 3;

    float acc[2][4][4];
#pragma unroll
    for (int mi = 0; mi < 2; mi++)
#pragma unroll
        for (int ni = 0; ni < 4; ni++)
#pragma unroll
            for (int r = 0; r < 4; r++) acc[mi][ni][r] = 0.f;

    for (int kc = 0; kc < NFEAT; kc += 32) {
        __syncthreads();
#pragma unroll
        for (int t = 0; t < 4; t++) {
            int f4  = tid + t * 256;
            int row = f4 >> 3;
            int c4  = (f4 & 7) * 4;
            int gm  = m0 + row;
            float4 v = make_float4(0.f, 0.f, 0.f, 0.f);
            if (gm < N_NODES)
                v = *reinterpret_cast<const float4*>(&X[gm * NFEAT + kc + c4]);
            Xs[row][c4 + 0] = __uint_as_float(f2tf32(v.x));
            Xs[row][c4 + 1] = __uint_as_float(f2tf32(v.y));
            Xs[row][c4 + 2] = __uint_as_float(f2tf32(v.z));
            Xs[row][c4 + 3] = __uint_as_float(f2tf32(v.w));
        }
#pragma unroll
        for (int t = 0; t < 2; t++) {
            int f4  = tid + t * 256;
            int row = f4 >> 4;
            int c4  = (f4 & 15) * 4;
            float4 v = *reinterpret_cast<const float4*>(&W[(kc + row) * NHID + c4]);
            Ws[row][c4 + 0] = __uint_as_float(f2tf32(v.x));
            Ws[row][c4 + 1] = __uint_as_float(f2tf32(v.y));
            Ws[row][c4 + 2] = __uint_as_float(f2tf32(v.z));
            Ws[row][c4 + 3] = __uint_as_float(f2tf32(v.w));
        }
        __syncthreads();

#pragma unroll
        for (int ks = 0; ks < 32; ks += 8) {
            uint32_t a[2][4];
#pragma unroll
            for (int mi = 0; mi < 2; mi++) {
                int base = wm * 32 + mi * 16;
                a[mi][0] = __float_as_uint(Xs[base + gr][ks + tg]);
                a[mi][1] = __float_as_uint(Xs[base + gr + 8][ks + tg]);
                a[mi][2] = __float_as_uint(Xs[base + gr][ks + tg + 4]);
                a[mi][3] = __float_as_uint(Xs[base + gr + 8][ks + tg + 4]);
            }
#pragma unroll
            for (int ni = 0; ni < 4; ni++) {
                int cb = wn * 32 + ni * 8;
                uint32_t b0 = __float_as_uint(Ws[ks + tg][cb + gr]);
                uint32_t b1 = __float_as_uint(Ws[ks + tg + 4][cb + gr]);
#pragma unroll
                for (int mi = 0; mi < 2; mi++) {
                    asm volatile(
                        "mma.sync.aligned.m16n8k8.row.col.f32.tf32.tf32.f32 "
                        "{%0,%1,%2,%3}, {%4,%5,%6,%7}, {%8,%9}, {%0,%1,%2,%3};"
                        : "+f"(acc[mi][ni][0]), "+f"(acc[mi][ni][1]),
                          "+f"(acc[mi][ni][2]), "+f"(acc[mi][ni][3])
                        : "r"(a[mi][0]), "r"(a[mi][1]), "r"(a[mi][2]), "r"(a[mi][3]),
                          "r"(b0), "r"(b1));
                }
            }
        }
    }

#pragma unroll
    for (int mi = 0; mi < 2; mi++) {
#pragma unroll
        for (int ni = 0; ni < 4; ni++) {
            int row = m0 + wm * 32 + mi * 16 + gr;
            int col = wn * 32 + ni * 8 + tg * 2;
            if (row < N_NODES)
                *reinterpret_cast<float2*>(&g_h1[row * NHID + col]) =
                    make_float2(acc[mi][ni][0], acc[mi][ni][1]);
            if (row + 8 < N_NODES)
                *reinterpret_cast<float2*>(&g_h1[(row + 8) * NHID + col]) =
                    make_float2(acc[mi][ni][2], acc[mi][ni][3]);
        }
    }
}

// ---------------------------------------------------------------------------
// scatter1: agg1[dst] += w * h1[src].  8 threads/edge, each handles 8 floats:
// 2x float4 gather + 2x red.global.add.v4.f32. Same REDG count as 16-thr
// version but half the threads and half the redundant index loads.
// ---------------------------------------------------------------------------
__global__ __launch_bounds__(256) void scatter1_kernel(const int* __restrict__ ei,
                                                       const float* __restrict__ ew) {
    int gid = blockIdx.x * blockDim.x + threadIdx.x;
    int e = gid >> 3;
    int c = gid & 7;
    if (e >= N_EDGES) return;
    int s = ei[e];
    int d = ei[N_EDGES + e];
    float w = ew[e];
    const float4* src = reinterpret_cast<const float4*>(&g_h1[s * NHID + c * 8]);
    float4 v0 = src[0];
    float4 v1 = src[1];
    float* dst = &g_agg1[d * NHID + c * 8];
    asm volatile("red.global.add.v4.f32 [%0], {%1, %2, %3, %4};"
                 :: "l"(dst), "f"(v0.x * w), "f"(v0.y * w), "f"(v0.z * w), "f"(v0.w * w)
                 : "memory");
    asm volatile("red.global.add.v4.f32 [%0], {%1, %2, %3, %4};"
                 :: "l"(dst + 4), "f"(v1.x * w), "f"(v1.y * w), "f"(v1.z * w), "f"(v1.w * w)
                 : "memory");
}

// ---------------------------------------------------------------------------
// GEMM2 (+fused ReLU): h2 = relu(agg1)[100000,64] @ W2[64,16], fp32 output.
// ONE thread per node (measured best: 19.2 us), row read exactly once,
// 16 outputs in 8 f32x2 accumulators.
// ---------------------------------------------------------------------------
__global__ __launch_bounds__(256) void gemm2_kernel(const float* __restrict__ W2) {
    __shared__ float Ws[NHID * NCLASS];  // [64][16] row-major, 1024 floats
    const int tid = threadIdx.x;
    reinterpret_cast<float4*>(Ws)[tid] = reinterpret_cast<const float4*>(W2)[tid];
    __syncthreads();

    int node = blockIdx.x * blockDim.x + tid;
    if (node >= N_NODES) return;

    unsigned long long acc[8] = {};      // 16 output cols as 8 pairs

#pragma unroll
    for (int k4 = 0; k4 < NHID / 4; k4++) {
        float4 a = *reinterpret_cast<const float4*>(&g_agg1[node * NHID + k4 * 4]);
        a.x = fmaxf(a.x, 0.f); a.y = fmaxf(a.y, 0.f);
        a.z = fmaxf(a.z, 0.f); a.w = fmaxf(a.w, 0.f);
#pragma unroll
        for (int j = 0; j < 4; j++) {
            float av = (j == 0) ? a.x : (j == 1) ? a.y : (j == 2) ? a.z : a.w;
            unsigned long long ap = pack2(av);
            const ulonglong2* wr = reinterpret_cast<const ulonglong2*>(
                &Ws[(k4 * 4 + j) * NCLASS]);
            ulonglong2 w01 = wr[0];
            ulonglong2 w23 = wr[1];
            ulonglong2 w45 = wr[2];
            ulonglong2 w67 = wr[3];
            fma2(acc[0], ap, w01.x); fma2(acc[1], ap, w01.y);
            fma2(acc[2], ap, w23.x); fma2(acc[3], ap, w23.y);
            fma2(acc[4], ap, w45.x); fma2(acc[5], ap, w45.y);
            fma2(acc[6], ap, w67.x); fma2(acc[7], ap, w67.y);
        }
    }

#pragma unroll
    for (int p = 0; p < 4; p++) {
        float2 lo = unpack2(acc[p * 2 + 0]);
        float2 hi = unpack2(acc[p * 2 + 1]);
        *reinterpret_cast<float4*>(&g_h2[node * NCLASS + p * 4]) =
            make_float4(lo.x, lo.y, hi.x, hi.y);
    }
}

// ---------------------------------------------------------------------------
// scatter2: out[dst] += w * h2[src].  4 threads/edge, float4 gather + red.v4.
// ---------------------------------------------------------------------------
__global__ __launch_bounds__(256) void scatter2_kernel(const int* __restrict__ ei,
                                                       const float* __restrict__ ew,
                                                       float* __restrict__ out) {
    int gid = blockIdx.x * blockDim.x + threadIdx.x;
    int e = gid >> 2;
    int c = gid & 3;
    if (e >= N_EDGES) return;
    int s = ei[e];
    int d = ei[N_EDGES + e];
    float w = ew[e];
    float4 v = *reinterpret_cast<const float4*>(&g_h2[s * NCLASS + c * 4]);
    float* dst = &out[d * NCLASS + c * 4];
    asm volatile("red.global.add.v4.f32 [%0], {%1, %2, %3, %4};"
                 :: "l"(dst), "f"(v.x * w), "f"(v.y * w), "f"(v.z * w), "f"(v.w * w)
                 : "memory");
}

// ---------------------------------------------------------------------------
extern "C" void kernel_launch(void* const* d_in, const int* in_sizes, int n_in,
                              void* d_out, int out_size) {
    const float* x   = (const float*)d_in[0];
    const int*   ei1 = (const int*)  d_in[1];
    const int*   ei2 = (const int*)  d_in[2];
    const float* ew1 = (const float*)d_in[3];
    const float* ew2 = (const float*)d_in[4];
    const float* W1  = (const float*)d_in[5];
    const float* W2  = (const float*)d_in[6];
    float* out = (float*)d_out;

    zero_kernel<<<2048, 256>>>(out);
    gemm1_kernel<<<(N_NODES + 127) / 128, 256>>>(x, W1);
    scatter1_kernel<<<(N_EDGES * 8 + 255) / 256, 256>>>(ei1, ew1);
    gemm2_kernel<<<(N_NODES + 255) / 256, 256>>>(W2);
    scatter2_kernel<<<(N_EDGES * 4 + 255) / 256, 256>>>(ei2, ew2, out);
}

// round 9
// speedup vs baseline: 2.1798x; 1.1657x over previous
#include <cuda_runtime.h>
#include <cstdint>

#define N_NODES 100000
#define N_EDGES 1600000
#define NFEAT   128
#define NHID    64
#define NCLASS  16

// Scratch (device globals — no allocation allowed in kernel_launch)
__device__ float g_h1[N_NODES * NHID];     // X @ W1 (fp32)
__device__ float g_agg1[N_NODES * NHID];   // scatter1 accumulator
__device__ float g_h2[N_NODES * NCLASS];   // relu(agg1) @ W2

// ---------------- f32x2 packed helpers (SASS FFMA2 — only via PTX) ----------
__device__ __forceinline__ void fma2(unsigned long long& d,
                                     unsigned long long a,
                                     unsigned long long b) {
    asm("fma.rn.f32x2 %0, %1, %2, %3;" : "=l"(d) : "l"(a), "l"(b), "l"(d));
}
__device__ __forceinline__ unsigned long long pack2(float a) {
    unsigned long long r;
    asm("mov.b64 %0, {%1, %1};" : "=l"(r) : "f"(a));
    return r;
}
__device__ __forceinline__ float2 unpack2(unsigned long long p) {
    float2 f;
    asm("mov.b64 {%0, %1}, %2;" : "=f"(f.x), "=f"(f.y) : "l"(p));
    return f;
}
__device__ __forceinline__ uint32_t f2tf32(float f) {
    uint32_t r;
    asm("cvt.rna.tf32.f32 %0, %1;" : "=r"(r) : "f"(f));
    return r;
}

// ---------------------------------------------------------------------------
// Zero agg1 and d_out (atomically accumulated; must start at 0 every launch).
// ---------------------------------------------------------------------------
__global__ void zero_kernel(float* __restrict__ out) {
    const int stride = gridDim.x * blockDim.x;
    int i = blockIdx.x * blockDim.x + threadIdx.x;
    const float4 z = make_float4(0.f, 0.f, 0.f, 0.f);
    const int n1 = N_NODES * NHID / 4;
    const int n2 = N_NODES * NCLASS / 4;
    for (int idx = i; idx < n1; idx += stride)
        reinterpret_cast<float4*>(g_agg1)[idx] = z;
    for (int idx = i; idx < n2; idx += stride)
        reinterpret_cast<float4*>(out)[idx] = z;
}

// ---------------------------------------------------------------------------
// GEMM1 (tf32 tensor cores): h1 = X[100000,128] @ W1[128,64], fp32 output.
// Block: 256 threads = 8 warps, tile 128(M) x 64(N), K chunks of 32.
// ---------------------------------------------------------------------------
__global__ __launch_bounds__(256) void gemm1_kernel(const float* __restrict__ X,
                                                    const float* __restrict__ W) {
    __shared__ float Xs[128][36];
    __shared__ float Ws[32][72];

    const int tid  = threadIdx.x;
    const int lane = tid & 31;
    const int warp = tid >> 5;
    const int m0   = blockIdx.x * 128;
    const int wm   = warp >> 1;
    const int wn   = warp & 1;
    const int gr   = lane >> 2;
    const int tg   = lane & 3;

    float acc[2][4][4];
#pragma unroll
    for (int mi = 0; mi < 2; mi++)
#pragma unroll
        for (int ni = 0; ni < 4; ni++)
#pragma unroll
            for (int r = 0; r < 4; r++) acc[mi][ni][r] = 0.f;

    for (int kc = 0; kc < NFEAT; kc += 32) {
        __syncthreads();
#pragma unroll
        for (int t = 0; t < 4; t++) {
            int f4  = tid + t * 256;
            int row = f4 >> 3;
            int c4  = (f4 & 7) * 4;
            int gm  = m0 + row;
            float4 v = make_float4(0.f, 0.f, 0.f, 0.f);
            if (gm < N_NODES)
                v = *reinterpret_cast<const float4*>(&X[gm * NFEAT + kc + c4]);
            Xs[row][c4 + 0] = __uint_as_float(f2tf32(v.x));
            Xs[row][c4 + 1] = __uint_as_float(f2tf32(v.y));
            Xs[row][c4 + 2] = __uint_as_float(f2tf32(v.z));
            Xs[row][c4 + 3] = __uint_as_float(f2tf32(v.w));
        }
#pragma unroll
        for (int t = 0; t < 2; t++) {
            int f4  = tid + t * 256;
            int row = f4 >> 4;
            int c4  = (f4 & 15) * 4;
            float4 v = *reinterpret_cast<const float4*>(&W[(kc + row) * NHID + c4]);
            Ws[row][c4 + 0] = __uint_as_float(f2tf32(v.x));
            Ws[row][c4 + 1] = __uint_as_float(f2tf32(v.y));
            Ws[row][c4 + 2] = __uint_as_float(f2tf32(v.z));
            Ws[row][c4 + 3] = __uint_as_float(f2tf32(v.w));
        }
        __syncthreads();

#pragma unroll
        for (int ks = 0; ks < 32; ks += 8) {
            uint32_t a[2][4];
#pragma unroll
            for (int mi = 0; mi < 2; mi++) {
                int base = wm * 32 + mi * 16;
                a[mi][0] = __float_as_uint(Xs[base + gr][ks + tg]);
                a[mi][1] = __float_as_uint(Xs[base + gr + 8][ks + tg]);
                a[mi][2] = __float_as_uint(Xs[base + gr][ks + tg + 4]);
                a[mi][3] = __float_as_uint(Xs[base + gr + 8][ks + tg + 4]);
            }
#pragma unroll
            for (int ni = 0; ni < 4; ni++) {
                int cb = wn * 32 + ni * 8;
                uint32_t b0 = __float_as_uint(Ws[ks + tg][cb + gr]);
                uint32_t b1 = __float_as_uint(Ws[ks + tg + 4][cb + gr]);
#pragma unroll
                for (int mi = 0; mi < 2; mi++) {
                    asm volatile(
                        "mma.sync.aligned.m16n8k8.row.col.f32.tf32.tf32.f32 "
                        "{%0,%1,%2,%3}, {%4,%5,%6,%7}, {%8,%9}, {%0,%1,%2,%3};"
                        : "+f"(acc[mi][ni][0]), "+f"(acc[mi][ni][1]),
                          "+f"(acc[mi][ni][2]), "+f"(acc[mi][ni][3])
                        : "r"(a[mi][0]), "r"(a[mi][1]), "r"(a[mi][2]), "r"(a[mi][3]),
                          "r"(b0), "r"(b1));
                }
            }
        }
    }

#pragma unroll
    for (int mi = 0; mi < 2; mi++) {
#pragma unroll
        for (int ni = 0; ni < 4; ni++) {
            int row = m0 + wm * 32 + mi * 16 + gr;
            int col = wn * 32 + ni * 8 + tg * 2;
            if (row < N_NODES)
                *reinterpret_cast<float2*>(&g_h1[row * NHID + col]) =
                    make_float2(acc[mi][ni][0], acc[mi][ni][1]);
            if (row + 8 < N_NODES)
                *reinterpret_cast<float2*>(&g_h1[(row + 8) * NHID + col]) =
                    make_float2(acc[mi][ni][2], acc[mi][ni][3]);
        }
    }
}

// ---------------------------------------------------------------------------
// scatter1: agg1[dst] += w * h1[src].  16 threads/edge, one float4 gather +
// one red.global.add.v4.f32 per thread (measured-best layout).
// ---------------------------------------------------------------------------
__global__ __launch_bounds__(256) void scatter1_kernel(const int* __restrict__ ei,
                                                       const float* __restrict__ ew) {
    int gid = blockIdx.x * blockDim.x + threadIdx.x;
    int e = gid >> 4;
    int c = gid & 15;
    if (e >= N_EDGES) return;
    int s = ei[e];
    int d = ei[N_EDGES + e];
    float w = ew[e];
    float4 v = *reinterpret_cast<const float4*>(&g_h1[s * NHID + c * 4]);
    float* dst = &g_agg1[d * NHID + c * 4];
    asm volatile("red.global.add.v4.f32 [%0], {%1, %2, %3, %4};"
                 :: "l"(dst), "f"(v.x * w), "f"(v.y * w), "f"(v.z * w), "f"(v.w * w)
                 : "memory");
}

// ---------------------------------------------------------------------------
// GEMM2 (+fused ReLU): h2 = relu(agg1)[100000,64] @ W2[64,16], fp32 output.
// ONE thread per node (measured best ~20 us), row read exactly once,
// 16 outputs in 8 f32x2 accumulators.
// ---------------------------------------------------------------------------
__global__ __launch_bounds__(256) void gemm2_kernel(const float* __restrict__ W2) {
    __shared__ float Ws[NHID * NCLASS];  // [64][16] row-major, 1024 floats
    const int tid = threadIdx.x;
    reinterpret_cast<float4*>(Ws)[tid] = reinterpret_cast<const float4*>(W2)[tid];
    __syncthreads();

    int node = blockIdx.x * blockDim.x + tid;
    if (node >= N_NODES) return;

    unsigned long long acc[8] = {};      // 16 output cols as 8 pairs

#pragma unroll
    for (int k4 = 0; k4 < NHID / 4; k4++) {
        float4 a = *reinterpret_cast<const float4*>(&g_agg1[node * NHID + k4 * 4]);
        a.x = fmaxf(a.x, 0.f); a.y = fmaxf(a.y, 0.f);
        a.z = fmaxf(a.z, 0.f); a.w = fmaxf(a.w, 0.f);
#pragma unroll
        for (int j = 0; j < 4; j++) {
            float av = (j == 0) ? a.x : (j == 1) ? a.y : (j == 2) ? a.z : a.w;
            unsigned long long ap = pack2(av);
            const ulonglong2* wr = reinterpret_cast<const ulonglong2*>(
                &Ws[(k4 * 4 + j) * NCLASS]);
            ulonglong2 w01 = wr[0];
            ulonglong2 w23 = wr[1];
            ulonglong2 w45 = wr[2];
            ulonglong2 w67 = wr[3];
            fma2(acc[0], ap, w01.x); fma2(acc[1], ap, w01.y);
            fma2(acc[2], ap, w23.x); fma2(acc[3], ap, w23.y);
            fma2(acc[4], ap, w45.x); fma2(acc[5], ap, w45.y);
            fma2(acc[6], ap, w67.x); fma2(acc[7], ap, w67.y);
        }
    }

#pragma unroll
    for (int p = 0; p < 4; p++) {
        float2 lo = unpack2(acc[p * 2 + 0]);
        float2 hi = unpack2(acc[p * 2 + 1]);
        *reinterpret_cast<float4*>(&g_h2[node * NCLASS + p * 4]) =
            make_float4(lo.x, lo.y, hi.x, hi.y);
    }
}

// ---------------------------------------------------------------------------
// scatter2: out[dst] += w * h2[src].  4 threads/edge, float4 gather + red.v4.
// ---------------------------------------------------------------------------
__global__ __launch_bounds__(256) void scatter2_kernel(const int* __restrict__ ei,
                                                       const float* __restrict__ ew,
                                                       float* __restrict__ out) {
    int gid = blockIdx.x * blockDim.x + threadIdx.x;
    int e = gid >> 2;
    int c = gid & 3;
    if (e >= N_EDGES) return;
    int s = ei[e];
    int d = ei[N_EDGES + e];
    float w = ew[e];
    float4 v = *reinterpret_cast<const float4*>(&g_h2[s * NCLASS + c * 4]);
    float* dst = &out[d * NCLASS + c * 4];
    asm volatile("red.global.add.v4.f32 [%0], {%1, %2, %3, %4};"
                 :: "l"(dst), "f"(v.x * w), "f"(v.y * w), "f"(v.z * w), "f"(v.w * w)
                 : "memory");
}

// ---------------------------------------------------------------------------
extern "C" void kernel_launch(void* const* d_in, const int* in_sizes, int n_in,
                              void* d_out, int out_size) {
    const float* x   = (const float*)d_in[0];
    const int*   ei1 = (const int*)  d_in[1];
    const int*   ei2 = (const int*)  d_in[2];
    const float* ew1 = (const float*)d_in[3];
    const float* ew2 = (const float*)d_in[4];
    const float* W1  = (const float*)d_in[5];
    const float* W2  = (const float*)d_in[6];
    float* out = (float*)d_out;

    zero_kernel<<<2048, 256>>>(out);
    gemm1_kernel<<<(N_NODES + 127) / 128, 256>>>(x, W1);
    scatter1_kernel<<<(N_EDGES * 16 + 255) / 256, 256>>>(ei1, ew1);
    gemm2_kernel<<<(N_NODES + 255) / 256, 256>>>(W2);
    scatter2_kernel<<<(N_EDGES * 4 + 255) / 256, 256>>>(ei2, ew2, out);
}